// round 15
// baseline (speedup 1.0000x reference)
#include <cuda_runtime.h>
#include <cuda_bf16.h>
#include <math.h>
#include <stdint.h>

#define BB   4
#define SS   1024
#define EE   4
#define HH   512
#define NHH  8
#define HDD  64
#define FFF  1024
#define LL   4
#define NTT  17
#define NR   63
#define NROWS (BB*SS)    // 4096

// ---------------- scratch ----------------
__device__ float g_x[NROWS*EE];
__device__ float g_xn[NROWS*HH];              // tf32-rounded LN output
__device__ __nv_bfloat16 g_qkvh[NROWS*2*HH];  // [row][q(512,pre-scaled) | k(512)] bf16
__device__ __nv_bfloat16 g_vT[NROWS*HH];      // [(b*NH+h)*HD+d][s] bf16
__device__ float g_ao[NROWS*HH];
__device__ float g_rsum[LL*NR];
__device__ int   g_mask[NROWS];
__device__ int   g_flags[4];
__device__ float g_wqkv[LL*HH*3*HH];          // tf32-rounded Wqkv

// ---------------- helpers ----------------
__device__ __forceinline__ unsigned f2tf(float f) {
    unsigned u; asm("cvt.rna.tf32.f32 %0, %1;" : "=r"(u) : "f"(f)); return u;
}
__device__ __forceinline__ unsigned pack_bf16(float lo, float hi) {
    unsigned r; asm("cvt.rn.bf16x2.f32 %0, %1, %2;" : "=r"(r) : "f"(hi), "f"(lo));
    return r;
}
__device__ __forceinline__ void mma8(float* c, unsigned a0, unsigned a1,
                                     unsigned a2, unsigned a3,
                                     unsigned b0, unsigned b1) {
    asm volatile(
        "mma.sync.aligned.m16n8k8.row.col.f32.tf32.tf32.f32 "
        "{%0,%1,%2,%3},{%4,%5,%6,%7},{%8,%9},{%0,%1,%2,%3};"
        : "+f"(c[0]), "+f"(c[1]), "+f"(c[2]), "+f"(c[3])
        : "r"(a0), "r"(a1), "r"(a2), "r"(a3), "r"(b0), "r"(b1));
}
__device__ __forceinline__ void mma16(float* c, unsigned a0, unsigned a1,
                                      unsigned a2, unsigned a3,
                                      unsigned b0, unsigned b1) {
    asm volatile(
        "mma.sync.aligned.m16n8k16.row.col.f32.bf16.bf16.f32 "
        "{%0,%1,%2,%3},{%4,%5,%6,%7},{%8,%9},{%0,%1,%2,%3};"
        : "+f"(c[0]), "+f"(c[1]), "+f"(c[2]), "+f"(c[3])
        : "r"(a0), "r"(a1), "r"(a2), "r"(a3), "r"(b0), "r"(b1));
}
__device__ __forceinline__ unsigned smem_u32(const void* p) {
    return (unsigned)__cvta_generic_to_shared(p);
}
__device__ __forceinline__ void cp16(unsigned s, const void* g) {
    asm volatile("cp.async.ca.shared.global [%0],[%1],16;\n" :: "r"(s), "l"(g));
}
__device__ __forceinline__ void cp_commit() { asm volatile("cp.async.commit_group;\n"); }
template<int N> __device__ __forceinline__ void cp_wait() {
    asm volatile("cp.async.wait_group %0;\n" :: "n"(N));
}

// ---------------- dtype detection ----------------
__global__ void detect_kernel(const unsigned int* __restrict__ maskw,
                              const unsigned int* __restrict__ patw) {
    __shared__ int fl[4];
    int tid = threadIdx.x;
    if (tid < 4) fl[tid] = 0;
    __syncthreads();
    for (int i = tid; i < 1024; i += 256) {
        unsigned int w = maskw[i];
        if ((w & 0xFFFFu) == 0x3F80u) atomicOr(&fl[0], 1);
        if (w == 0x3F800000u)         atomicOr(&fl[1], 1);
        if (w > 1u)                   atomicOr(&fl[2], 1);
        unsigned int p = patw[i];
        if (p > 16u)                  atomicOr(&fl[3], 1);
    }
    __syncthreads();
    if (tid < 4) g_flags[tid] = fl[tid];
}

// ---------------- embedding + mask ----------------
__global__ void embed_kernel(const void* __restrict__ maskp,
                             const void* __restrict__ patp,
                             const float* __restrict__ emb) {
    int i = blockIdx.x * blockDim.x + threadIdx.x;
    if (i >= NROWS) return;
    int fbf = g_flags[0], ff32 = g_flags[1], fu8 = g_flags[2], pf = g_flags[3];
    int m;
    if (fbf)       m = (((const unsigned short*)maskp)[i] != 0);
    else if (ff32) m = (((const float*)maskp)[i] != 0.0f);
    else if (fu8)  m = (((const unsigned char*)maskp)[i] != 0);
    else           m = (((const int*)maskp)[i] != 0);
    int p;
    if (pf) p = (int)(((const float*)patp)[i]);
    else    p = ((const int*)patp)[i];
    g_mask[i] = m;
    int src = m ? (NTT - 1) : p;
    #pragma unroll
    for (int e = 0; e < EE; e++)
        g_x[i*EE + e] = emb[src*EE + e];
}

// ---------------- relemb row sums ----------------
__global__ void rsum_kernel(const float* __restrict__ relemb) {
    int idx = threadIdx.x + blockIdx.x * blockDim.x;
    if (idx >= LL*NR) return;
    const float* p = relemb + (size_t)idx * HDD;
    float s = 0.f;
    #pragma unroll
    for (int d = 0; d < HDD; d++) s += p[d];
    g_rsum[idx] = s;
}

// ---------------- Wqkv -> tf32-rounded copy ----------------
__global__ void round_w_kernel(const float* __restrict__ W) {
    int i = blockIdx.x * blockDim.x + threadIdx.x;
    float4 v = ((const float4*)W)[i];
    v.x = __uint_as_float(f2tf(v.x));
    v.y = __uint_as_float(f2tf(v.y));
    v.z = __uint_as_float(f2tf(v.z));
    v.w = __uint_as_float(f2tf(v.w));
    ((float4*)g_wqkv)[i] = v;
}

// ---------------- xp = x@Wi + bi ; xn = tf32(LN(xp))  (layer 0 only) ----------
__global__ void proj_ln_kernel(const float* __restrict__ Wi,
                               const float* __restrict__ bi,
                               const float* __restrict__ g1,
                               const float* __restrict__ b1n,
                               int l) {
    int row = blockIdx.x;
    int tid = threadIdx.x;
    const float* W = Wi + (size_t)l*EE*HH;
    const float* bl = bi + (size_t)l*HH;
    const float* gl = g1 + (size_t)l*HH;
    const float* bn = b1n + (size_t)l*HH;
    float x0 = g_x[row*EE+0], x1 = g_x[row*EE+1], x2 = g_x[row*EE+2], x3 = g_x[row*EE+3];
    float xp[4];
    float s = 0.f, sq = 0.f;
    #pragma unroll
    for (int u = 0; u < 4; u++) {
        int j = tid + u*128;
        float v = bl[j] + x0*W[j] + x1*W[HH+j] + x2*W[2*HH+j] + x3*W[3*HH+j];
        xp[u] = v; s += v; sq += v*v;
    }
    #pragma unroll
    for (int off = 16; off > 0; off >>= 1) {
        s  += __shfl_down_sync(0xffffffffu, s,  off);
        sq += __shfl_down_sync(0xffffffffu, sq, off);
    }
    __shared__ float rs[4], rq[4];
    __shared__ float smean, sinv;
    if ((tid & 31) == 0) { rs[tid>>5] = s; rq[tid>>5] = sq; }
    __syncthreads();
    if (tid == 0) {
        float S = rs[0]+rs[1]+rs[2]+rs[3];
        float Q = rq[0]+rq[1]+rq[2]+rq[3];
        float m = S * (1.f/HH);
        float var = Q * (1.f/HH) - m*m;
        smean = m; sinv = rsqrtf(var + 1e-5f);
    }
    __syncthreads();
    float m = smean, inv = sinv;
    #pragma unroll
    for (int u = 0; u < 4; u++) {
        int j = tid + u*128;
        g_xn[(size_t)row*HH + j] =
            __uint_as_float(f2tf((xp[u]-m)*inv*gl[j] + bn[j]));
    }
}

// ---------------- qkv GEMM (tf32 mma, cp.async 3-stage); bf16 epilogue ---------
#define AST 36
#define BST 72
#define GEMM_SMEM_FLOATS (3*128*AST + 3*32*BST + 64)
#define GEMM_SMEM_BYTES  (GEMM_SMEM_FLOATS*4)
__global__ void __launch_bounds__(256)
gemm_qkv_kernel(int l, const float* __restrict__ bias_all) {
    extern __shared__ float sm[];
    float* As = sm;                          // 3 x 128*AST
    float* Bs = sm + 3*128*AST;              // 3 x 32*BST
    float* bsm = sm + 3*128*AST + 3*32*BST;

    const int N = 3*HH, K = HH;
    const float* W = g_wqkv + (size_t)l*HH*3*HH;
    const float* bias = bias_all + (size_t)l*3*HH;

    int tid = threadIdx.x;
    int w = tid >> 5, lane = tid & 31;
    int g = lane >> 2, t4 = lane & 3;
    int row0 = blockIdx.y * 128, col0 = blockIdx.x * 64;

    if (tid < 64) bsm[tid] = bias[col0 + tid];

    auto issue = [&](int stage) {
        int buf = stage % 3;
        int k0 = stage * 32;
        float* Ab = As + buf*128*AST;
        float* Bb = Bs + buf*32*BST;
        #pragma unroll
        for (int i = 0; i < 4; i++) {
            int id = tid + i*256;
            int r = id >> 3, c = id & 7;
            cp16(smem_u32(&Ab[r*AST + c*4]), &g_xn[(size_t)(row0+r)*K + k0 + c*4]);
        }
        #pragma unroll
        for (int i = 0; i < 2; i++) {
            int id = tid + i*256;
            int r = id >> 4, c = id & 15;
            cp16(smem_u32(&Bb[r*BST + c*4]), &W[(size_t)(k0+r)*N + col0 + c*4]);
        }
    };

    float c[8][4];
    #pragma unroll
    for (int nt = 0; nt < 8; nt++)
        #pragma unroll
        for (int j = 0; j < 4; j++) c[nt][j] = 0.f;

    issue(0); cp_commit();
    issue(1); cp_commit();
    for (int s = 0; s < 16; s++) {
        if (s < 15) cp_wait<1>(); else cp_wait<0>();
        __syncthreads();
        const float* A = As + (s % 3)*128*AST;
        const float* B = Bs + (s % 3)*32*BST;
        #pragma unroll
        for (int kk = 0; kk < 32; kk += 8) {
            int ab = (w*16 + g)*AST + kk + t4;
            unsigned a0 = __float_as_uint(A[ab]);
            unsigned a1 = __float_as_uint(A[ab + 8*AST]);
            unsigned a2 = __float_as_uint(A[ab + 4]);
            unsigned a3 = __float_as_uint(A[ab + 8*AST + 4]);
            #pragma unroll
            for (int nt = 0; nt < 8; nt++) {
                unsigned b0 = __float_as_uint(B[(kk+t4)*BST + nt*8 + g]);
                unsigned b1 = __float_as_uint(B[(kk+t4+4)*BST + nt*8 + g]);
                mma8(c[nt], a0, a1, a2, a3, b0, b1);
            }
        }
        if (s < 14) { issue(s+2); cp_commit(); }
    }
    int grow0 = row0 + w*16 + g;
    #pragma unroll
    for (int nt = 0; nt < 8; nt++) {
        int lc = nt*8 + 2*t4;
        int gcol = col0 + lc;
        float b0v = bsm[lc], b1v = bsm[lc+1];
        float c00 = c[nt][0] + b0v, c01 = c[nt][1] + b1v;
        float c10 = c[nt][2] + b0v, c11 = c[nt][3] + b1v;
        if (col0 < 2*HH) {
            float s = (col0 < HH) ? 0.125f : 1.0f;
            *(unsigned*)&g_qkvh[(size_t)grow0*(2*HH) + gcol]     = pack_bf16(s*c00, s*c01);
            *(unsigned*)&g_qkvh[(size_t)(grow0+8)*(2*HH) + gcol] = pack_bf16(s*c10, s*c11);
        } else {
            int hd = gcol - 2*HH;
            int h = hd >> 6, d = hd & 63;
            int bb = grow0 >> 10, s0 = grow0 & 1023;
            size_t base = ((size_t)((bb*NHH + h)*HDD + d))*SS;
            g_vT[base + s0]          = __float2bfloat16(c00);
            g_vT[base + SS + s0]     = __float2bfloat16(c01);
            g_vT[base + s0 + 8]      = __float2bfloat16(c10);
            g_vT[base + SS + s0 + 8] = __float2bfloat16(c11);
        }
    }
}

// ---------------- flash attention: bf16 m16n8k16, 3-stage, Q in registers ------
#define QSU 36
#define OFF_KSU (128*QSU)
#define OFF_VSU (OFF_KSU + 3*64*QSU)
#define OFF_RBU (OFF_VSU + 3*64*QSU)
#define OFF_MKU (OFF_RBU + 64)
#define ATT_SMEM_U32   (OFF_MKU + 3*64)
#define ATT_SMEM_BYTES (ATT_SMEM_U32*4)
__global__ void __launch_bounds__(256, 2) attn_kernel(int l) {
    extern __shared__ unsigned smu[];
    unsigned* qs = smu;
    unsigned* ks = smu + OFF_KSU;
    unsigned* vs = smu + OFF_VSU;
    float*    rb = (float*)(smu + OFF_RBU);
    int*     mki = (int*)(smu + OFF_MKU);

    const int qt = blockIdx.x, h = blockIdx.y, b = blockIdx.z;
    const int tid = threadIdx.x;
    const int w = tid >> 5, lane = tid & 31;
    const int g = lane >> 2, t4 = lane & 3;

    if (tid < NR) rb[tid] = g_rsum[l*NR + tid];

    const __nv_bfloat16* qp = g_qkvh + (size_t)(b*SS + qt*128)*(2*HH) + h*HDD;

    auto issue = [&](int stage) {
        int buf = stage % 3;
        const __nv_bfloat16* kp = g_qkvh + (size_t)(b*SS + stage*64)*(2*HH) + HH + h*HDD;
        const __nv_bfloat16* vp = g_vT + ((size_t)((b*NHH + h)*HDD))*SS + stage*64;
        unsigned* kb = ks + buf*64*QSU;
        unsigned* vb = vs + buf*64*QSU;
        #pragma unroll
        for (int i = 0; i < 2; i++) {
            int id = tid + i*256;           // 512 chunks: 64 rows x 8 (16B each)
            int r = id >> 3, c = id & 7;
            cp16(smem_u32(&kb[r*QSU + c*4]), kp + (size_t)r*(2*HH) + c*8);
            cp16(smem_u32(&vb[r*QSU + c*4]), vp + (size_t)r*SS + c*8);
        }
        if (tid < 16)
            cp16(smem_u32(&mki[buf*64 + tid*4]), &g_mask[b*SS + stage*64 + tid*4]);
    };

    // prologue: Q group, then stages 0 and 1
    #pragma unroll
    for (int i = 0; i < 4; i++) {
        int id = tid + i*256;
        int r = id >> 3, c = id & 7;
        cp16(smem_u32(&qs[r*QSU + c*4]), qp + (size_t)r*(2*HH) + c*8);
    }
    cp_commit();
    issue(0); cp_commit();
    issue(1); cp_commit();

    const int lr0 = w*16 + g;
    const int qrow0 = qt*128 + lr0;
    const int qrow1 = qrow0 + 8;

    // Q fragments -> registers (once)
    cp_wait<2>();
    __syncthreads();
    unsigned qa[4][4];
    #pragma unroll
    for (int kc = 0; kc < 4; kc++) {
        int ab = lr0*QSU + kc*8 + t4;
        qa[kc][0] = qs[ab];
        qa[kc][1] = qs[ab + 8*QSU];
        qa[kc][2] = qs[ab + 4];
        qa[kc][3] = qs[ab + 8*QSU + 4];
    }

    float o[8][4];
    #pragma unroll
    for (int nt = 0; nt < 8; nt++)
        #pragma unroll
        for (int j = 0; j < 4; j++) o[nt][j] = 0.f;
    float m0 = -1e30f, m1 = -1e30f, l0 = 0.f, l1 = 0.f;

    for (int kt = 0; kt < 16; kt++) {
        if (kt < 15) cp_wait<1>(); else cp_wait<0>();
        __syncthreads();
        const int buf = kt % 3;
        const unsigned* kb = ks + buf*64*QSU;
        const unsigned* vb = vs + buf*64*QSU;
        const int*      mb = mki + buf*64;

        // ---- S = Q K^T  (bf16 k16) ----
        float sc[8][4];
        #pragma unroll
        for (int nt = 0; nt < 8; nt++)
            #pragma unroll
            for (int j = 0; j < 4; j++) sc[nt][j] = 0.f;
        #pragma unroll
        for (int kc = 0; kc < 4; kc++) {
            #pragma unroll
            for (int nt = 0; nt < 8; nt++) {
                int bbase = (nt*8 + g)*QSU + kc*8 + t4;
                mma16(sc[nt], qa[kc][0], qa[kc][1], qa[kc][2], qa[kc][3],
                      kb[bbase], kb[bbase + 4]);
            }
        }

        // ---- bias + mask; row maxima (Q pre-scaled by 1/8) ----
        float mx0 = -1e30f, mx1 = -1e30f;
        #pragma unroll
        for (int nt = 0; nt < 8; nt++) {
            #pragma unroll
            for (int jj = 0; jj < 2; jj++) {
                int cc = nt*8 + 2*t4 + jj;
                int krow = kt*64 + cc;
                int mflag = mb[cc];
                int d0 = qrow0 - krow + 31; d0 = d0 < 0 ? 0 : (d0 > 62 ? 62 : d0);
                float v0 = sc[nt][jj] + rb[d0];
                if (mflag && qrow0 != krow) v0 = -1e30f;
                sc[nt][jj] = v0; mx0 = fmaxf(mx0, v0);
                int d1 = qrow1 - krow + 31; d1 = d1 < 0 ? 0 : (d1 > 62 ? 62 : d1);
                float v1 = sc[nt][jj+2] + rb[d1];
                if (mflag && qrow1 != krow) v1 = -1e30f;
                sc[nt][jj+2] = v1; mx1 = fmaxf(mx1, v1);
            }
        }
        #pragma unroll
        for (int off = 1; off < 4; off <<= 1) {
            mx0 = fmaxf(mx0, __shfl_xor_sync(0xffffffffu, mx0, off));
            mx1 = fmaxf(mx1, __shfl_xor_sync(0xffffffffu, mx1, off));
        }
        float mn0 = fmaxf(m0, mx0), mn1 = fmaxf(m1, mx1);
        float cf0 = __expf(m0 - mn0), cf1 = __expf(m1 - mn1);
        m0 = mn0; m1 = mn1;
        #pragma unroll
        for (int nt = 0; nt < 8; nt++) {
            o[nt][0] *= cf0; o[nt][1] *= cf0;
            o[nt][2] *= cf1; o[nt][3] *= cf1;
        }

        // ---- P = exp(S-m); C-frag == A-frag for bf16 ----
        float s0 = 0.f, s1 = 0.f;
        #pragma unroll
        for (int nt = 0; nt < 8; nt++) {
            float p00 = (sc[nt][0] > -1e29f) ? __expf(sc[nt][0] - m0) : 0.f;
            float p01 = (sc[nt][1] > -1e29f) ? __expf(sc[nt][1] - m0) : 0.f;
            float p10 = (sc[nt][2] > -1e29f) ? __expf(sc[nt][2] - m1) : 0.f;
            float p11 = (sc[nt][3] > -1e29f) ? __expf(sc[nt][3] - m1) : 0.f;
            s0 += p00 + p01; s1 += p10 + p11;
            sc[nt][0] = p00; sc[nt][1] = p01; sc[nt][2] = p10; sc[nt][3] = p11;
        }
        #pragma unroll
        for (int off = 1; off < 4; off <<= 1) {
            s0 += __shfl_xor_sync(0xffffffffu, s0, off);
            s1 += __shfl_xor_sync(0xffffffffu, s1, off);
        }
        l0 = l0*cf0 + s0; l1 = l1*cf1 + s1;

        // ---- O += P V ----
        #pragma unroll
        for (int j = 0; j < 4; j++) {
            unsigned a0 = pack_bf16(sc[2*j][0],   sc[2*j][1]);
            unsigned a1 = pack_bf16(sc[2*j][2],   sc[2*j][3]);
            unsigned a2 = pack_bf16(sc[2*j+1][0], sc[2*j+1][1]);
            unsigned a3 = pack_bf16(sc[2*j+1][2], sc[2*j+1][3]);
            #pragma unroll
            for (int ont = 0; ont < 8; ont++) {
                int bbase = (ont*8 + g)*QSU + j*8 + t4;
                mma16(o[ont], a0, a1, a2, a3, vb[bbase], vb[bbase + 4]);
            }
        }
        if (kt < 14) { issue(kt+2); cp_commit(); }
    }

    float inv0 = 1.f / l0, inv1 = 1.f / l1;
    float* aop = g_ao + (size_t)(b*SS + qt*128)*HH + h*HDD;
    #pragma unroll
    for (int nt = 0; nt < 8; nt++) {
        int cc = nt*8 + 2*t4;
        *(float2*)&aop[(size_t)lr0*HH + cc]     = make_float2(o[nt][0]*inv0, o[nt][1]*inv0);
        *(float2*)&aop[(size_t)(lr0+8)*HH + cc] = make_float2(o[nt][2]*inv1, o[nt][3]*inv1);
    }
}

// ------- post-attn fused: x update + FFN + residual + NEXT layer's proj_ln -----
__global__ void __launch_bounds__(128) post_attn_kernel(
        const float* __restrict__ Wo,  const float* __restrict__ bo,
        const float* __restrict__ g2,  const float* __restrict__ b2n,
        const float* __restrict__ Wf1, const float* __restrict__ bf1,
        const float* __restrict__ Wf2, const float* __restrict__ bf2,
        const float* __restrict__ Wi,  const float* __restrict__ bi,
        const float* __restrict__ g1,  const float* __restrict__ b1n,
        int l) {
    int w = threadIdx.x >> 5, lane = threadIdx.x & 31;
    int row = blockIdx.x * 4 + w;

    const float4* Wo4 = (const float4*)(Wo + (size_t)l*HH*EE);
    float4 acc = make_float4(0.f,0.f,0.f,0.f);
    for (int k = lane; k < HH; k += 32) {
        float a = g_ao[(size_t)row*HH + k];
        float4 wv = Wo4[k];
        acc.x += a*wv.x; acc.y += a*wv.y; acc.z += a*wv.z; acc.w += a*wv.w;
    }
    #pragma unroll
    for (int off = 16; off > 0; off >>= 1) {
        acc.x += __shfl_down_sync(0xffffffffu, acc.x, off);
        acc.y += __shfl_down_sync(0xffffffffu, acc.y, off);
        acc.z += __shfl_down_sync(0xffffffffu, acc.z, off);
        acc.w += __shfl_down_sync(0xffffffffu, acc.w, off);
    }
    float t0=0,t1=0,t2=0,t3=0, xn0=0,xn1=0,xn2=0,xn3=0;
    if (lane == 0) {
        t0 = g_x[row*EE+0] + acc.x + bo[l*EE+0];
        t1 = g_x[row*EE+1] + acc.y + bo[l*EE+1];
        t2 = g_x[row*EE+2] + acc.z + bo[l*EE+2];
        t3 = g_x[row*EE+3] + acc.w + bo[l*EE+3];
        float m = (t0+t1+t2+t3)*0.25f;
        float d0=t0-m, d1=t1-m, d2=t2-m, d3=t3-m;
        float var = (d0*d0+d1*d1+d2*d2+d3*d3)*0.25f;
        float inv = rsqrtf(var + 1e-5f);
        xn0 = d0*inv*g2[l*EE+0] + b2n[l*EE+0];
        xn1 = d1*inv*g2[l*EE+1] + b2n[l*EE+1];
        xn2 = d2*inv*g2[l*EE+2] + b2n[l*EE+2];
        xn3 = d3*inv*g2[l*EE+3] + b2n[l*EE+3];
    }
    xn0 = __shfl_sync(0xffffffffu, xn0, 0);
    xn1 = __shfl_sync(0xffffffffu, xn1, 0);
    xn2 = __shfl_sync(0xffffffffu, xn2, 0);
    xn3 = __shfl_sync(0xffffffffu, xn3, 0);

    const float* W1 = Wf1 + (size_t)l*EE*FFF;
    const float* b1 = bf1 + (size_t)l*FFF;
    const float4* W2 = (const float4*)(Wf2 + (size_t)l*FFF*EE);
    float4 f = make_float4(0.f,0.f,0.f,0.f);
    for (int j = lane; j < FFF; j += 32) {
        float hv = b1[j] + xn0*W1[j] + xn1*W1[FFF+j] + xn2*W1[2*FFF+j] + xn3*W1[3*FFF+j];
        hv = fmaxf(hv, 0.f);
        float4 wv = W2[j];
        f.x += hv*wv.x; f.y += hv*wv.y; f.z += hv*wv.z; f.w += hv*wv.w;
    }
    #pragma unroll
    for (int off = 16; off > 0; off >>= 1) {
        f.x += __shfl_down_sync(0xffffffffu, f.x, off);
        f.y += __shfl_down_sync(0xffffffffu, f.y, off);
        f.z += __shfl_down_sync(0xffffffffu, f.z, off);
        f.w += __shfl_down_sync(0xffffffffu, f.w, off);
    }
    float nx0=0,nx1=0,nx2=0,nx3=0;
    if (lane == 0) {
        nx0 = t0 + f.x + bf2[l*EE+0];
        nx1 = t1 + f.y + bf2[l*EE+1];
        nx2 = t2 + f.z + bf2[l*EE+2];
        nx3 = t3 + f.w + bf2[l*EE+3];
        g_x[row*EE+0] = nx0;
        g_x[row*EE+1] = nx1;
        g_x[row*EE+2] = nx2;
        g_x[row*EE+3] = nx3;
    }
    if (l >= LL-1) return;

    // ---- fused proj_ln for layer l+1 ----
    nx0 = __shfl_sync(0xffffffffu, nx0, 0);
    nx1 = __shfl_sync(0xffffffffu, nx1, 0);
    nx2 = __shfl_sync(0xffffffffu, nx2, 0);
    nx3 = __shfl_sync(0xffffffffu, nx3, 0);

    int ln = l + 1;
    const float* Wp = Wi + (size_t)ln*EE*HH;
    const float* bl = bi + (size_t)ln*HH;
    const float* gl = g1 + (size_t)ln*HH;
    const float* bn = b1n + (size_t)ln*HH;
    float xp[16];
    float s = 0.f, sq = 0.f;
    #pragma unroll
    for (int u = 0; u < 16; u++) {
        int j = lane + u*32;
        float v = bl[j] + nx0*Wp[j] + nx1*Wp[HH+j] + nx2*Wp[2*HH+j] + nx3*Wp[3*HH+j];
        xp[u] = v; s += v; sq += v*v;
    }
    #pragma unroll
    for (int off = 16; off > 0; off >>= 1) {
        s  += __shfl_xor_sync(0xffffffffu, s,  off);
        sq += __shfl_xor_sync(0xffffffffu, sq, off);
    }
    float m = s * (1.f/HH);
    float var = sq * (1.f/HH) - m*m;
    float inv = rsqrtf(var + 1e-5f);
    #pragma unroll
    for (int u = 0; u < 16; u++) {
        int j = lane + u*32;
        g_xn[(size_t)row*HH + j] =
            __uint_as_float(f2tf((xp[u]-m)*inv*gl[j] + bn[j]));
    }
}

// ---------------- out = x @ Wout + bout ----------------
__global__ void out_kernel(const float* __restrict__ Wout,
                           const float* __restrict__ bout,
                           float* __restrict__ out, int total) {
    int i = blockIdx.x * blockDim.x + threadIdx.x;
    if (i >= total) return;
    int r = i / NTT, n = i % NTT;
    float acc = bout[n];
    #pragma unroll
    for (int e = 0; e < 4; e++) acc += g_x[r*EE+e]*Wout[e*NTT+n];
    out[i] = acc;
}

// ---------------- launch ----------------
extern "C" void kernel_launch(void* const* d_in, const int* in_sizes, int n_in,
                              void* d_out, int out_size) {
    const float* emb    = (const float*)d_in[2];
    const float* Wi     = (const float*)d_in[3];
    const float* bi     = (const float*)d_in[4];
    const float* Wqkv   = (const float*)d_in[5];
    const float* bqkv   = (const float*)d_in[6];
    const float* Wo     = (const float*)d_in[7];
    const float* bo     = (const float*)d_in[8];
    const float* g1     = (const float*)d_in[9];
    const float* b1n    = (const float*)d_in[10];
    const float* Wf1    = (const float*)d_in[11];
    const float* bf1    = (const float*)d_in[12];
    const float* Wf2    = (const float*)d_in[13];
    const float* bf2    = (const float*)d_in[14];
    const float* g2     = (const float*)d_in[15];
    const float* b2n    = (const float*)d_in[16];
    const float* relemb = (const float*)d_in[17];
    const float* Wout   = (const float*)d_in[18];
    const float* bout   = (const float*)d_in[19];

    cudaFuncSetAttribute(attn_kernel, cudaFuncAttributeMaxDynamicSharedMemorySize, ATT_SMEM_BYTES);
    cudaFuncSetAttribute(gemm_qkv_kernel, cudaFuncAttributeMaxDynamicSharedMemorySize, GEMM_SMEM_BYTES);

    detect_kernel<<<1, 256>>>((const unsigned int*)d_in[1], (const unsigned int*)d_in[0]);
    embed_kernel<<<NROWS/256, 256>>>(d_in[1], d_in[0], emb);
    rsum_kernel<<<1, 256>>>(relemb);
    round_w_kernel<<<(LL*HH*3*HH/4)/256, 256>>>(Wqkv);

    proj_ln_kernel<<<NROWS, 128>>>(Wi, bi, g1, b1n, 0);
    for (int l = 0; l < LL; l++) {
        gemm_qkv_kernel<<<dim3((3*HH)/64, NROWS/128), 256, GEMM_SMEM_BYTES>>>(l, bqkv);
        attn_kernel<<<dim3(SS/128, NHH, BB), 256, ATT_SMEM_BYTES>>>(l);
        post_attn_kernel<<<NROWS/4, 128>>>(Wo, bo, g2, b2n, Wf1, bf1, Wf2, bf2,
                                           Wi, bi, g1, b1n, l);
    }
    out_kernel<<<(NROWS*NTT + 255)/256, 256>>>(Wout, bout, (float*)d_out, NROWS*NTT);
}

// round 17
// speedup vs baseline: 1.2713x; 1.2713x over previous
#include <cuda_runtime.h>
#include <cuda_fp16.h>
#include <math.h>
#include <stdint.h>

#define BB   4
#define SS   1024
#define EE   4
#define HH   512
#define NHH  8
#define HDD  64
#define FFF  1024
#define LL   4
#define NTT  17
#define NR   63
#define NROWS (BB*SS)    // 4096

// ---------------- scratch ----------------
__device__ float g_x[NROWS*EE];
__device__ __half g_xnh[NROWS*HH];            // fp16 LN output
__device__ __half g_qkvh[NROWS*2*HH];         // [row][q(512,pre-scaled) | k(512)] fp16
__device__ __half g_vT[NROWS*HH];             // [(b*NH+h)*HD+d][s] fp16
__device__ float g_ao[NROWS*HH];
__device__ float g_rsum[LL*NR];
__device__ int   g_mask[NROWS];
__device__ int   g_flags[4];
__device__ __half g_wqkvTh[LL*3*HH*HH];       // fp16, TRANSPOSED: [l][n][k]

// ---------------- helpers ----------------
__device__ __forceinline__ unsigned pack_f16(float lo, float hi) {
    unsigned r; asm("cvt.rn.f16x2.f32 %0, %1, %2;" : "=r"(r) : "f"(hi), "f"(lo));
    return r;
}
__device__ __forceinline__ void mma16h(float* c, unsigned a0, unsigned a1,
                                       unsigned a2, unsigned a3,
                                       unsigned b0, unsigned b1) {
    asm volatile(
        "mma.sync.aligned.m16n8k16.row.col.f32.f16.f16.f32 "
        "{%0,%1,%2,%3},{%4,%5,%6,%7},{%8,%9},{%0,%1,%2,%3};"
        : "+f"(c[0]), "+f"(c[1]), "+f"(c[2]), "+f"(c[3])
        : "r"(a0), "r"(a1), "r"(a2), "r"(a3), "r"(b0), "r"(b1));
}
__device__ __forceinline__ unsigned smem_u32(const void* p) {
    return (unsigned)__cvta_generic_to_shared(p);
}
__device__ __forceinline__ void cp16(unsigned s, const void* g) {
    asm volatile("cp.async.ca.shared.global [%0],[%1],16;\n" :: "r"(s), "l"(g));
}
__device__ __forceinline__ void cp_commit() { asm volatile("cp.async.commit_group;\n"); }
template<int N> __device__ __forceinline__ void cp_wait() {
    asm volatile("cp.async.wait_group %0;\n" :: "n"(N));
}

// ---------------- dtype detection ----------------
__global__ void detect_kernel(const unsigned int* __restrict__ maskw,
                              const unsigned int* __restrict__ patw) {
    __shared__ int fl[4];
    int tid = threadIdx.x;
    if (tid < 4) fl[tid] = 0;
    __syncthreads();
    for (int i = tid; i < 1024; i += 256) {
        unsigned int w = maskw[i];
        if ((w & 0xFFFFu) == 0x3F80u) atomicOr(&fl[0], 1);
        if (w == 0x3F800000u)         atomicOr(&fl[1], 1);
        if (w > 1u)                   atomicOr(&fl[2], 1);
        unsigned int p = patw[i];
        if (p > 16u)                  atomicOr(&fl[3], 1);
    }
    __syncthreads();
    if (tid < 4) g_flags[tid] = fl[tid];
}

// ---------------- embedding + mask ----------------
__global__ void embed_kernel(const void* __restrict__ maskp,
                             const void* __restrict__ patp,
                             const float* __restrict__ emb) {
    int i = blockIdx.x * blockDim.x + threadIdx.x;
    if (i >= NROWS) return;
    int fbf = g_flags[0], ff32 = g_flags[1], fu8 = g_flags[2], pf = g_flags[3];
    int m;
    if (fbf)       m = (((const unsigned short*)maskp)[i] != 0);
    else if (ff32) m = (((const float*)maskp)[i] != 0.0f);
    else if (fu8)  m = (((const unsigned char*)maskp)[i] != 0);
    else           m = (((const int*)maskp)[i] != 0);
    int p;
    if (pf) p = (int)(((const float*)patp)[i]);
    else    p = ((const int*)patp)[i];
    g_mask[i] = m;
    int src = m ? (NTT - 1) : p;
    #pragma unroll
    for (int e = 0; e < EE; e++)
        g_x[i*EE + e] = emb[src*EE + e];
}

// ---------------- relemb row sums ----------------
__global__ void rsum_kernel(const float* __restrict__ relemb) {
    int idx = threadIdx.x + blockIdx.x * blockDim.x;
    if (idx >= LL*NR) return;
    const float* p = relemb + (size_t)idx * HDD;
    float s = 0.f;
    #pragma unroll
    for (int d = 0; d < HDD; d++) s += p[d];
    g_rsum[idx] = s;
}

// ---------- Wqkv -> fp16 TRANSPOSED copy: g_wqkvTh[l][n][k] ----------
__global__ void round_wT_kernel(const float* __restrict__ W) {
    __shared__ float t[32][33];
    int l = blockIdx.z;
    int n0 = blockIdx.x * 32, k0 = blockIdx.y * 32;
    int tx = threadIdx.x, ty = threadIdx.y;   // 32 x 8
    const float* Wl = W + (size_t)l*HH*3*HH;
    #pragma unroll
    for (int i = 0; i < 4; i++)
        t[ty + 8*i][tx] = Wl[(size_t)(k0 + ty + 8*i)*(3*HH) + n0 + tx];
    __syncthreads();
    __half* T = g_wqkvTh + (size_t)l*3*HH*HH;
    #pragma unroll
    for (int i = 0; i < 4; i++)
        T[(size_t)(n0 + ty + 8*i)*HH + k0 + tx] = __float2half_rn(t[tx][ty + 8*i]);
}

// ---------------- xp = x@Wi + bi ; xn = fp16(LN(xp))  (layer 0 only) ----------
__global__ void proj_ln_kernel(const float* __restrict__ Wi,
                               const float* __restrict__ bi,
                               const float* __restrict__ g1,
                               const float* __restrict__ b1n,
                               int l) {
    int row = blockIdx.x;
    int tid = threadIdx.x;
    const float* W = Wi + (size_t)l*EE*HH;
    const float* bl = bi + (size_t)l*HH;
    const float* gl = g1 + (size_t)l*HH;
    const float* bn = b1n + (size_t)l*HH;
    float x0 = g_x[row*EE+0], x1 = g_x[row*EE+1], x2 = g_x[row*EE+2], x3 = g_x[row*EE+3];
    float xp[4];
    float s = 0.f, sq = 0.f;
    #pragma unroll
    for (int u = 0; u < 4; u++) {
        int j = tid + u*128;
        float v = bl[j] + x0*W[j] + x1*W[HH+j] + x2*W[2*HH+j] + x3*W[3*HH+j];
        xp[u] = v; s += v; sq += v*v;
    }
    #pragma unroll
    for (int off = 16; off > 0; off >>= 1) {
        s  += __shfl_down_sync(0xffffffffu, s,  off);
        sq += __shfl_down_sync(0xffffffffu, sq, off);
    }
    __shared__ float rs[4], rq[4];
    __shared__ float smean, sinv;
    if ((tid & 31) == 0) { rs[tid>>5] = s; rq[tid>>5] = sq; }
    __syncthreads();
    if (tid == 0) {
        float S = rs[0]+rs[1]+rs[2]+rs[3];
        float Q = rq[0]+rq[1]+rq[2]+rq[3];
        float m = S * (1.f/HH);
        float var = Q * (1.f/HH) - m*m;
        smean = m; sinv = rsqrtf(var + 1e-5f);
    }
    __syncthreads();
    float m = smean, inv = sinv;
    #pragma unroll
    for (int u = 0; u < 4; u++) {
        int j = tid + u*128;
        g_xnh[(size_t)row*HH + j] = __float2half_rn((xp[u]-m)*inv*gl[j] + bn[j]);
    }
}

// ======= qkv GEMM: fp16 m16n8k16, 3-stage cp.async, M=128 x N=64 tile =======
#define GAST 36                               // u32 stride for 64-fp16 rows
#define GQ3 (128*GAST)
#define GB3 (64*GAST)
#define OFF_GB   (3*GQ3)
#define OFF_GBIAS (3*GQ3 + 3*GB3)
#define GEMMH_SMEM_U32   (OFF_GBIAS + 64)
#define GEMMH_SMEM_BYTES (GEMMH_SMEM_U32*4)
__global__ void __launch_bounds__(256)
gemm_qkv_h(int l, const float* __restrict__ bias_all) {
    extern __shared__ unsigned gsm[];
    unsigned* As = gsm;                       // 3 x 128*GAST
    unsigned* Bs = gsm + OFF_GB;              // 3 x 64*GAST
    float*   bsm = (float*)(gsm + OFF_GBIAS);

    int tid = threadIdx.x;
    int w = tid >> 5, lane = tid & 31;
    int g = lane >> 2, t4 = lane & 3;
    int row0 = blockIdx.y * 128, col0 = blockIdx.x * 64;

    const __half* Ag = g_xnh + (size_t)row0*HH;
    const __half* Bg = g_wqkvTh + (size_t)l*3*HH*HH + (size_t)col0*HH;
    const float* bias = bias_all + (size_t)l*3*HH;
    if (tid < 64) bsm[tid] = bias[col0 + tid];

    auto issue = [&](int s) {
        int buf = s % 3;
        int k0 = s * 64;
        unsigned* Ab = As + buf*GQ3;
        unsigned* Bb = Bs + buf*GB3;
        #pragma unroll
        for (int i = 0; i < 4; i++) {
            int id = tid + i*256;             // 1024 chunks: 128 rows x 8 (16B)
            int r = id >> 3, c = id & 7;
            cp16(smem_u32(&Ab[r*GAST + c*4]), Ag + (size_t)r*HH + k0 + c*8);
        }
        #pragma unroll
        for (int i = 0; i < 2; i++) {
            int id = tid + i*256;             // 512 chunks: 64 rows x 8
            int r = id >> 3, c = id & 7;
            cp16(smem_u32(&Bb[r*GAST + c*4]), Bg + (size_t)r*HH + k0 + c*8);
        }
    };

    float c[8][4];
    #pragma unroll
    for (int nt = 0; nt < 8; nt++)
        #pragma unroll
        for (int j = 0; j < 4; j++) c[nt][j] = 0.f;

    issue(0); cp_commit();
    issue(1); cp_commit();
    const int lr0 = w*16 + g;
    for (int s = 0; s < 8; s++) {
        if (s < 7) cp_wait<1>(); else cp_wait<0>();
        __syncthreads();
        const unsigned* Ab = As + (s % 3)*GQ3;
        const unsigned* Bb = Bs + (s % 3)*GB3;
        #pragma unroll
        for (int kc = 0; kc < 4; kc++) {
            int ab = lr0*GAST + kc*8 + t4;
            unsigned a0 = Ab[ab];
            unsigned a1 = Ab[ab + 8*GAST];
            unsigned a2 = Ab[ab + 4];
            unsigned a3 = Ab[ab + 8*GAST + 4];
            #pragma unroll
            for (int nt = 0; nt < 8; nt++) {
                int bb = (nt*8 + g)*GAST + kc*8 + t4;
                mma16h(c[nt], a0, a1, a2, a3, Bb[bb], Bb[bb + 4]);
            }
        }
        if (s < 6) { issue(s+2); cp_commit(); }
    }

    int grow0 = row0 + lr0;
    #pragma unroll
    for (int nt = 0; nt < 8; nt++) {
        int lc = nt*8 + 2*t4;
        int gcol = col0 + lc;
        float b0v = bsm[lc], b1v = bsm[lc+1];
        float c00 = c[nt][0] + b0v, c01 = c[nt][1] + b1v;
        float c10 = c[nt][2] + b0v, c11 = c[nt][3] + b1v;
        if (col0 < 2*HH) {
            // q (pre-scaled by 1/8) and k -> g_qkvh fp16
            float sc = (col0 < HH) ? 0.125f : 1.0f;
            *(unsigned*)&g_qkvh[(size_t)grow0*(2*HH) + gcol]     = pack_f16(sc*c00, sc*c01);
            *(unsigned*)&g_qkvh[(size_t)(grow0+8)*(2*HH) + gcol] = pack_f16(sc*c10, sc*c11);
        } else {
            // v -> g_vT[(b*NH+h)*HD+d][s] (transposed scatter)
            int hd = gcol - 2*HH;
            int h = hd >> 6, d = hd & 63;
            int bb = grow0 >> 10, s0 = grow0 & 1023;
            size_t base = ((size_t)((bb*NHH + h)*HDD + d))*SS;
            g_vT[base + s0]          = __float2half_rn(c00);
            g_vT[base + SS + s0]     = __float2half_rn(c01);
            g_vT[base + s0 + 8]      = __float2half_rn(c10);
            g_vT[base + SS + s0 + 8] = __float2half_rn(c11);
        }
    }
}

// ---------------- flash attention: fp16 m16n8k16, 3-stage, Q in registers ------
#define QSU 36
#define OFF_KSU (128*QSU)
#define OFF_VSU (OFF_KSU + 3*64*QSU)
#define OFF_RBU (OFF_VSU + 3*64*QSU)
#define OFF_MKU (OFF_RBU + 64)
#define ATT_SMEM_U32   (OFF_MKU + 3*64)
#define ATT_SMEM_BYTES (ATT_SMEM_U32*4)
__global__ void __launch_bounds__(256, 2) attn_kernel(int l) {
    extern __shared__ unsigned smu[];
    unsigned* qs = smu;
    unsigned* ks = smu + OFF_KSU;
    unsigned* vs = smu + OFF_VSU;
    float*    rb = (float*)(smu + OFF_RBU);
    int*     mki = (int*)(smu + OFF_MKU);

    const int qt = blockIdx.x, h = blockIdx.y, b = blockIdx.z;
    const int tid = threadIdx.x;
    const int w = tid >> 5, lane = tid & 31;
    const int g = lane >> 2, t4 = lane & 3;

    if (tid < NR) rb[tid] = g_rsum[l*NR + tid];

    const __half* qp = g_qkvh + (size_t)(b*SS + qt*128)*(2*HH) + h*HDD;

    auto issue = [&](int stage) {
        int buf = stage % 3;
        const __half* kp = g_qkvh + (size_t)(b*SS + stage*64)*(2*HH) + HH + h*HDD;
        const __half* vp = g_vT + ((size_t)((b*NHH + h)*HDD))*SS + stage*64;
        unsigned* kb = ks + buf*64*QSU;
        unsigned* vb = vs + buf*64*QSU;
        #pragma unroll
        for (int i = 0; i < 2; i++) {
            int id = tid + i*256;
            int r = id >> 3, c = id & 7;
            cp16(smem_u32(&kb[r*QSU + c*4]), kp + (size_t)r*(2*HH) + c*8);
            cp16(smem_u32(&vb[r*QSU + c*4]), vp + (size_t)r*SS + c*8);
        }
        if (tid < 16)
            cp16(smem_u32(&mki[buf*64 + tid*4]), &g_mask[b*SS + stage*64 + tid*4]);
    };

    #pragma unroll
    for (int i = 0; i < 4; i++) {
        int id = tid + i*256;
        int r = id >> 3, c = id & 7;
        cp16(smem_u32(&qs[r*QSU + c*4]), qp + (size_t)r*(2*HH) + c*8);
    }
    cp_commit();
    issue(0); cp_commit();
    issue(1); cp_commit();

    const int lr0 = w*16 + g;
    const int qrow0 = qt*128 + lr0;
    const int qrow1 = qrow0 + 8;

    cp_wait<2>();
    __syncthreads();
    unsigned qa[4][4];
    #pragma unroll
    for (int kc = 0; kc < 4; kc++) {
        int ab = lr0*QSU + kc*8 + t4;
        qa[kc][0] = qs[ab];
        qa[kc][1] = qs[ab + 8*QSU];
        qa[kc][2] = qs[ab + 4];
        qa[kc][3] = qs[ab + 8*QSU + 4];
    }

    float o[8][4];
    #pragma unroll
    for (int nt = 0; nt < 8; nt++)
        #pragma unroll
        for (int j = 0; j < 4; j++) o[nt][j] = 0.f;
    float m0 = -1e30f, m1 = -1e30f, l0 = 0.f, l1 = 0.f;

    for (int kt = 0; kt < 16; kt++) {
        if (kt < 15) cp_wait<1>(); else cp_wait<0>();
        __syncthreads();
        const int buf = kt % 3;
        const unsigned* kb = ks + buf*64*QSU;
        const unsigned* vb = vs + buf*64*QSU;
        const int*      mb = mki + buf*64;

        float sc[8][4];
        #pragma unroll
        for (int nt = 0; nt < 8; nt++)
            #pragma unroll
            for (int j = 0; j < 4; j++) sc[nt][j] = 0.f;
        #pragma unroll
        for (int kc = 0; kc < 4; kc++) {
            #pragma unroll
            for (int nt = 0; nt < 8; nt++) {
                int bbase = (nt*8 + g)*QSU + kc*8 + t4;
                mma16h(sc[nt], qa[kc][0], qa[kc][1], qa[kc][2], qa[kc][3],
                       kb[bbase], kb[bbase + 4]);
            }
        }

        float mx0 = -1e30f, mx1 = -1e30f;
        #pragma unroll
        for (int nt = 0; nt < 8; nt++) {
            #pragma unroll
            for (int jj = 0; jj < 2; jj++) {
                int cc = nt*8 + 2*t4 + jj;
                int krow = kt*64 + cc;
                int mflag = mb[cc];
                int d0 = qrow0 - krow + 31; d0 = d0 < 0 ? 0 : (d0 > 62 ? 62 : d0);
                float v0 = sc[nt][jj] + rb[d0];
                if (mflag && qrow0 != krow) v0 = -1e30f;
                sc[nt][jj] = v0; mx0 = fmaxf(mx0, v0);
                int d1 = qrow1 - krow + 31; d1 = d1 < 0 ? 0 : (d1 > 62 ? 62 : d1);
                float v1 = sc[nt][jj+2] + rb[d1];
                if (mflag && qrow1 != krow) v1 = -1e30f;
                sc[nt][jj+2] = v1; mx1 = fmaxf(mx1, v1);
            }
        }
        #pragma unroll
        for (int off = 1; off < 4; off <<= 1) {
            mx0 = fmaxf(mx0, __shfl_xor_sync(0xffffffffu, mx0, off));
            mx1 = fmaxf(mx1, __shfl_xor_sync(0xffffffffu, mx1, off));
        }
        float mn0 = fmaxf(m0, mx0), mn1 = fmaxf(m1, mx1);
        float cf0 = __expf(m0 - mn0), cf1 = __expf(m1 - mn1);
        m0 = mn0; m1 = mn1;
        #pragma unroll
        for (int nt = 0; nt < 8; nt++) {
            o[nt][0] *= cf0; o[nt][1] *= cf0;
            o[nt][2] *= cf1; o[nt][3] *= cf1;
        }

        float s0 = 0.f, s1 = 0.f;
        #pragma unroll
        for (int nt = 0; nt < 8; nt++) {
            float p00 = (sc[nt][0] > -1e29f) ? __expf(sc[nt][0] - m0) : 0.f;
            float p01 = (sc[nt][1] > -1e29f) ? __expf(sc[nt][1] - m0) : 0.f;
            float p10 = (sc[nt][2] > -1e29f) ? __expf(sc[nt][2] - m1) : 0.f;
            float p11 = (sc[nt][3] > -1e29f) ? __expf(sc[nt][3] - m1) : 0.f;
            s0 += p00 + p01; s1 += p10 + p11;
            sc[nt][0] = p00; sc[nt][1] = p01; sc[nt][2] = p10; sc[nt][3] = p11;
        }
        #pragma unroll
        for (int off = 1; off < 4; off <<= 1) {
            s0 += __shfl_xor_sync(0xffffffffu, s0, off);
            s1 += __shfl_xor_sync(0xffffffffu, s1, off);
        }
        l0 = l0*cf0 + s0; l1 = l1*cf1 + s1;

        #pragma unroll
        for (int j = 0; j < 4; j++) {
            unsigned a0 = pack_f16(sc[2*j][0],   sc[2*j][1]);
            unsigned a1 = pack_f16(sc[2*j][2],   sc[2*j][3]);
            unsigned a2 = pack_f16(sc[2*j+1][0], sc[2*j+1][1]);
            unsigned a3 = pack_f16(sc[2*j+1][2], sc[2*j+1][3]);
            #pragma unroll
            for (int ont = 0; ont < 8; ont++) {
                int bbase = (ont*8 + g)*QSU + j*8 + t4;
                mma16h(o[ont], a0, a1, a2, a3, vb[bbase], vb[bbase + 4]);
            }
        }
        if (kt < 14) { issue(kt+2); cp_commit(); }
    }

    float inv0 = 1.f / l0, inv1 = 1.f / l1;
    float* aop = g_ao + (size_t)(b*SS + qt*128)*HH + h*HDD;
    #pragma unroll
    for (int nt = 0; nt < 8; nt++) {
        int cc = nt*8 + 2*t4;
        *(float2*)&aop[(size_t)lr0*HH + cc]     = make_float2(o[nt][0]*inv0, o[nt][1]*inv0);
        *(float2*)&aop[(size_t)(lr0+8)*HH + cc] = make_float2(o[nt][2]*inv1, o[nt][3]*inv1);
    }
}

// ------- post-attn fused: x update + FFN + residual + NEXT layer's proj_ln -----
__global__ void __launch_bounds__(128) post_attn_kernel(
        const float* __restrict__ Wo,  const float* __restrict__ bo,
        const float* __restrict__ g2,  const float* __restrict__ b2n,
        const float* __restrict__ Wf1, const float* __restrict__ bf1,
        const float* __restrict__ Wf2, const float* __restrict__ bf2,
        const float* __restrict__ Wi,  const float* __restrict__ bi,
        const float* __restrict__ g1,  const float* __restrict__ b1n,
        int l) {
    int w = threadIdx.x >> 5, lane = threadIdx.x & 31;
    int row = blockIdx.x * 4 + w;

    const float4* Wo4 = (const float4*)(Wo + (size_t)l*HH*EE);
    float4 acc = make_float4(0.f,0.f,0.f,0.f);
    for (int k = lane; k < HH; k += 32) {
        float a = g_ao[(size_t)row*HH + k];
        float4 wv = Wo4[k];
        acc.x += a*wv.x; acc.y += a*wv.y; acc.z += a*wv.z; acc.w += a*wv.w;
    }
    #pragma unroll
    for (int off = 16; off > 0; off >>= 1) {
        acc.x += __shfl_down_sync(0xffffffffu, acc.x, off);
        acc.y += __shfl_down_sync(0xffffffffu, acc.y, off);
        acc.z += __shfl_down_sync(0xffffffffu, acc.z, off);
        acc.w += __shfl_down_sync(0xffffffffu, acc.w, off);
    }
    float t0=0,t1=0,t2=0,t3=0, xn0=0,xn1=0,xn2=0,xn3=0;
    if (lane == 0) {
        t0 = g_x[row*EE+0] + acc.x + bo[l*EE+0];
        t1 = g_x[row*EE+1] + acc.y + bo[l*EE+1];
        t2 = g_x[row*EE+2] + acc.z + bo[l*EE+2];
        t3 = g_x[row*EE+3] + acc.w + bo[l*EE+3];
        float m = (t0+t1+t2+t3)*0.25f;
        float d0=t0-m, d1=t1-m, d2=t2-m, d3=t3-m;
        float var = (d0*d0+d1*d1+d2*d2+d3*d3)*0.25f;
        float inv = rsqrtf(var + 1e-5f);
        xn0 = d0*inv*g2[l*EE+0] + b2n[l*EE+0];
        xn1 = d1*inv*g2[l*EE+1] + b2n[l*EE+1];
        xn2 = d2*inv*g2[l*EE+2] + b2n[l*EE+2];
        xn3 = d3*inv*g2[l*EE+3] + b2n[l*EE+3];
    }
    xn0 = __shfl_sync(0xffffffffu, xn0, 0);
    xn1 = __shfl_sync(0xffffffffu, xn1, 0);
    xn2 = __shfl_sync(0xffffffffu, xn2, 0);
    xn3 = __shfl_sync(0xffffffffu, xn3, 0);

    const float* W1 = Wf1 + (size_t)l*EE*FFF;
    const float* b1 = bf1 + (size_t)l*FFF;
    const float4* W2 = (const float4*)(Wf2 + (size_t)l*FFF*EE);
    float4 f = make_float4(0.f,0.f,0.f,0.f);
    for (int j = lane; j < FFF; j += 32) {
        float hv = b1[j] + xn0*W1[j] + xn1*W1[FFF+j] + xn2*W1[2*FFF+j] + xn3*W1[3*FFF+j];
        hv = fmaxf(hv, 0.f);
        float4 wv = W2[j];
        f.x += hv*wv.x; f.y += hv*wv.y; f.z += hv*wv.z; f.w += hv*wv.w;
    }
    #pragma unroll
    for (int off = 16; off > 0; off >>= 1) {
        f.x += __shfl_down_sync(0xffffffffu, f.x, off);
        f.y += __shfl_down_sync(0xffffffffu, f.y, off);
        f.z += __shfl_down_sync(0xffffffffu, f.z, off);
        f.w += __shfl_down_sync(0xffffffffu, f.w, off);
    }
    float nx0=0,nx1=0,nx2=0,nx3=0;
    if (lane == 0) {
        nx0 = t0 + f.x + bf2[l*EE+0];
        nx1 = t1 + f.y + bf2[l*EE+1];
        nx2 = t2 + f.z + bf2[l*EE+2];
        nx3 = t3 + f.w + bf2[l*EE+3];
        g_x[row*EE+0] = nx0;
        g_x[row*EE+1] = nx1;
        g_x[row*EE+2] = nx2;
        g_x[row*EE+3] = nx3;
    }
    if (l >= LL-1) return;

    nx0 = __shfl_sync(0xffffffffu, nx0, 0);
    nx1 = __shfl_sync(0xffffffffu, nx1, 0);
    nx2 = __shfl_sync(0xffffffffu, nx2, 0);
    nx3 = __shfl_sync(0xffffffffu, nx3, 0);

    int ln = l + 1;
    const float* Wp = Wi + (size_t)ln*EE*HH;
    const float* bl = bi + (size_t)ln*HH;
    const float* gl = g1 + (size_t)ln*HH;
    const float* bn = b1n + (size_t)ln*HH;
    float xp[16];
    float s = 0.f, sq = 0.f;
    #pragma unroll
    for (int u = 0; u < 16; u++) {
        int j = lane + u*32;
        float v = bl[j] + nx0*Wp[j] + nx1*Wp[HH+j] + nx2*Wp[2*HH+j] + nx3*Wp[3*HH+j];
        xp[u] = v; s += v; sq += v*v;
    }
    #pragma unroll
    for (int off = 16; off > 0; off >>= 1) {
        s  += __shfl_xor_sync(0xffffffffu, s,  off);
        sq += __shfl_xor_sync(0xffffffffu, sq, off);
    }
    float m = s * (1.f/HH);
    float var = sq * (1.f/HH) - m*m;
    float inv = rsqrtf(var + 1e-5f);
    #pragma unroll
    for (int u = 0; u < 16; u++) {
        int j = lane + u*32;
        g_xnh[(size_t)row*HH + j] = __float2half_rn((xp[u]-m)*inv*gl[j] + bn[j]);
    }
}

// ---------------- out = x @ Wout + bout ----------------
__global__ void out_kernel(const float* __restrict__ Wout,
                           const float* __restrict__ bout,
                           float* __restrict__ out, int total) {
    int i = blockIdx.x * blockDim.x + threadIdx.x;
    if (i >= total) return;
    int r = i / NTT, n = i % NTT;
    float acc = bout[n];
    #pragma unroll
    for (int e = 0; e < 4; e++) acc += g_x[r*EE+e]*Wout[e*NTT+n];
    out[i] = acc;
}

// ---------------- launch ----------------
extern "C" void kernel_launch(void* const* d_in, const int* in_sizes, int n_in,
                              void* d_out, int out_size) {
    const float* emb    = (const float*)d_in[2];
    const float* Wi     = (const float*)d_in[3];
    const float* bi     = (const float*)d_in[4];
    const float* Wqkv   = (const float*)d_in[5];
    const float* bqkv   = (const float*)d_in[6];
    const float* Wo     = (const float*)d_in[7];
    const float* bo     = (const float*)d_in[8];
    const float* g1     = (const float*)d_in[9];
    const float* b1n    = (const float*)d_in[10];
    const float* Wf1    = (const float*)d_in[11];
    const float* bf1    = (const float*)d_in[12];
    const float* Wf2    = (const float*)d_in[13];
    const float* bf2    = (const float*)d_in[14];
    const float* g2     = (const float*)d_in[15];
    const float* b2n    = (const float*)d_in[16];
    const float* relemb = (const float*)d_in[17];
    const float* Wout   = (const float*)d_in[18];
    const float* bout   = (const float*)d_in[19];

    cudaFuncSetAttribute(attn_kernel, cudaFuncAttributeMaxDynamicSharedMemorySize, ATT_SMEM_BYTES);
    cudaFuncSetAttribute(gemm_qkv_h, cudaFuncAttributeMaxDynamicSharedMemorySize, GEMMH_SMEM_BYTES);

    detect_kernel<<<1, 256>>>((const unsigned int*)d_in[1], (const unsigned int*)d_in[0]);
    embed_kernel<<<NROWS/256, 256>>>(d_in[1], d_in[0], emb);
    rsum_kernel<<<1, 256>>>(relemb);
    round_wT_kernel<<<dim3((3*HH)/32, HH/32, LL), dim3(32, 8)>>>(Wqkv);

    proj_ln_kernel<<<NROWS, 128>>>(Wi, bi, g1, b1n, 0);
    for (int l = 0; l < LL; l++) {
        gemm_qkv_h<<<dim3((3*HH)/64, NROWS/128), 256, GEMMH_SMEM_BYTES>>>(l, bqkv);
        attn_kernel<<<dim3(SS/128, NHH, BB), 256, ATT_SMEM_BYTES>>>(l);
        post_attn_kernel<<<NROWS/4, 128>>>(Wo, bo, g2, b2n, Wf1, bf1, Wf2, bf2,
                                           Wi, bi, g1, b1n, l);
    }
    out_kernel<<<(NROWS*NTT + 255)/256, 256>>>(Wout, bout, (float*)d_out, NROWS*NTT);
}